// round 7
// baseline (speedup 1.0000x reference)
#include <cuda_runtime.h>
#include <math.h>

#define SEQ 2048
#define DM  1024
#define NH  16
#define HD  64
#define LAT 256

// Scratch — device globals (no allocation allowed).
__device__ float g_q[SEQ * DM];
__device__ float g_ckv[SEQ * LAT];
__device__ float g_k[SEQ * DM];
__device__ float g_v[SEQ * DM];
__device__ float g_ctx[SEQ * DM];
__device__ float g_p[NH * SEQ * SEQ];   // 268 MB: per-head exp(QK^T) matrices

// --------------------------------------------------------------------------
// tf32 helpers
// --------------------------------------------------------------------------
__device__ __forceinline__ unsigned f2tf(float x) {
    unsigned r;
    asm("cvt.rna.tf32.f32 %0, %1;" : "=r"(r) : "f"(x));
    return r;
}

__device__ __forceinline__ void mma_tf32(float* c, const unsigned* a, const unsigned* b) {
    asm volatile(
        "mma.sync.aligned.m16n8k8.row.col.f32.tf32.tf32.f32 "
        "{%0,%1,%2,%3}, {%4,%5,%6,%7}, {%8,%9}, {%0,%1,%2,%3};"
        : "+f"(c[0]), "+f"(c[1]), "+f"(c[2]), "+f"(c[3])
        : "r"(a[0]), "r"(a[1]), "r"(a[2]), "r"(a[3]),
          "r"(b[0]), "r"(b[1]));
}

// --------------------------------------------------------------------------
// tf32 tensor-core GEMM — proven config (23.5us / 4.3GF = 183 TF/s).
// CTA tile 128x128, BK=32, 8 warps (4m x 2n), warp tile 32x64.
// --------------------------------------------------------------------------
#define AP 36
#define BP 132
__global__ __launch_bounds__(256) void gemm_tc(
    const float* __restrict__ A, const float* __restrict__ B,
    const float* __restrict__ bias, float* __restrict__ C,
    int M, int N, int K, int lda, int ldb, int ldc)
{
    __shared__ unsigned As[128 * AP];
    __shared__ unsigned Bs[32 * BP];

    const int tid  = threadIdx.x;
    const int lane = tid & 31;
    const int warp = tid >> 5;
    const int g = lane >> 2;
    const int r = lane & 3;
    const int wm = warp & 3;
    const int wn = warp >> 2;

    const int m0 = blockIdx.y * 128;
    const int n0 = blockIdx.x * 128;
    const int z  = blockIdx.z;
    B += (long)z * K * N;
    C += (long)z * N;
    const float* bptr = bias ? bias + (long)z * N : nullptr;

    float acc[2][8][4];
    #pragma unroll
    for (int i = 0; i < 2; i++)
        #pragma unroll
        for (int j = 0; j < 8; j++)
            #pragma unroll
            for (int t = 0; t < 4; t++) acc[i][j][t] = 0.f;

    for (int k0 = 0; k0 < K; k0 += 32) {
        #pragma unroll
        for (int e = 0; e < 16; e++) {
            int idx = e * 256 + tid;
            int m = idx >> 5, kk = idx & 31;
            As[m * AP + kk] = f2tf(A[(long)(m0 + m) * lda + k0 + kk]);
        }
        #pragma unroll
        for (int e = 0; e < 16; e++) {
            int idx = e * 256 + tid;
            int kk = idx >> 7, n = idx & 127;
            Bs[kk * BP + n] = f2tf(B[(long)(k0 + kk) * ldb + n0 + n]);
        }
        __syncthreads();

        #pragma unroll
        for (int ks = 0; ks < 4; ks++) {
            const int k = ks * 8;
            unsigned a[2][4], b[8][2];
            #pragma unroll
            for (int i = 0; i < 2; i++) {
                int row = wm * 32 + i * 16;
                a[i][0] = As[(row + g)     * AP + k + r];
                a[i][1] = As[(row + g + 8) * AP + k + r];
                a[i][2] = As[(row + g)     * AP + k + r + 4];
                a[i][3] = As[(row + g + 8) * AP + k + r + 4];
            }
            #pragma unroll
            for (int j = 0; j < 8; j++) {
                int col = wn * 64 + j * 8;
                b[j][0] = Bs[(k + r)     * BP + col + g];
                b[j][1] = Bs[(k + r + 4) * BP + col + g];
            }
            #pragma unroll
            for (int i = 0; i < 2; i++)
                #pragma unroll
                for (int j = 0; j < 8; j++)
                    mma_tf32(acc[i][j], a[i], b[j]);
        }
        __syncthreads();
    }

    #pragma unroll
    for (int i = 0; i < 2; i++) {
        int row = m0 + wm * 32 + i * 16;
        #pragma unroll
        for (int j = 0; j < 8; j++) {
            int col = n0 + wn * 64 + j * 8 + 2 * r;
            float b0 = 0.f, b1 = 0.f;
            if (bptr) { b0 = bptr[col]; b1 = bptr[col + 1]; }
            float2 v0 = make_float2(acc[i][j][0] + b0, acc[i][j][1] + b1);
            float2 v1 = make_float2(acc[i][j][2] + b0, acc[i][j][3] + b1);
            *reinterpret_cast<float2*>(&C[(long)(row + g)     * ldc + col]) = v0;
            *reinterpret_cast<float2*>(&C[(long)(row + g + 8) * ldc + col]) = v1;
        }
    }
}

// --------------------------------------------------------------------------
// score_exp: P[h, q0:q0+128, k0:k0+128] = exp( (Q*scale) @ K^T )
// One CTA per (key-tile, query-tile, head). K=64, single staging round.
// Qs/Ks [128][68]: fragment reads fully conflict-free (4g+r distinct).
// --------------------------------------------------------------------------
#define SP 68
__global__ __launch_bounds__(256) void score_exp(
    const float* __restrict__ q, const float* __restrict__ k,
    float* __restrict__ p)
{
    extern __shared__ unsigned ssm[];
    unsigned* Qs = ssm;               // 128*68
    unsigned* Ks = ssm + 128 * SP;    // 128*68

    const int tid  = threadIdx.x;
    const int lane = tid & 31;
    const int warp = tid >> 5;
    const int g = lane >> 2;
    const int r = lane & 3;
    const int wm = warp & 3;
    const int wn = warp >> 2;

    const int k0 = blockIdx.x * 128;
    const int q0 = blockIdx.y * 128;
    const int h  = blockIdx.z;
    float* ph = p + (size_t)h * SEQ * SEQ;

    // Stage Q (pre-scaled) and K tiles: coalesced float4 reads.
    #pragma unroll
    for (int e = 0; e < 8; e++) {
        int m  = e * 16 + (tid >> 4);
        int f4 = tid & 15;
        float4 q4 = *reinterpret_cast<const float4*>(
            &q[(size_t)(q0 + m) * DM + h * HD + f4 * 4]);
        float4 k4 = *reinterpret_cast<const float4*>(
            &k[(size_t)(k0 + m) * DM + h * HD + f4 * 4]);
        unsigned* qp = &Qs[m * SP + f4 * 4];
        qp[0] = f2tf(q4.x * 0.125f);
        qp[1] = f2tf(q4.y * 0.125f);
        qp[2] = f2tf(q4.z * 0.125f);
        qp[3] = f2tf(q4.w * 0.125f);
        unsigned* kp = &Ks[m * SP + f4 * 4];
        kp[0] = f2tf(k4.x);
        kp[1] = f2tf(k4.y);
        kp[2] = f2tf(k4.z);
        kp[3] = f2tf(k4.w);
    }
    __syncthreads();

    float acc[2][8][4];
    #pragma unroll
    for (int i = 0; i < 2; i++)
        #pragma unroll
        for (int j = 0; j < 8; j++)
            #pragma unroll
            for (int t = 0; t < 4; t++) acc[i][j][t] = 0.f;

    #pragma unroll
    for (int kt = 0; kt < 8; kt++) {
        const int kk = kt * 8;
        unsigned a[2][4], b[8][2];
        #pragma unroll
        for (int i = 0; i < 2; i++) {
            int row = wm * 32 + i * 16;
            a[i][0] = Qs[(row + g)     * SP + kk + r];
            a[i][1] = Qs[(row + g + 8) * SP + kk + r];
            a[i][2] = Qs[(row + g)     * SP + kk + r + 4];
            a[i][3] = Qs[(row + g + 8) * SP + kk + r + 4];
        }
        #pragma unroll
        for (int j = 0; j < 8; j++) {
            int col = wn * 64 + j * 8;
            b[j][0] = Ks[(col + g) * SP + kk + r];
            b[j][1] = Ks[(col + g) * SP + kk + r + 4];
        }
        #pragma unroll
        for (int i = 0; i < 2; i++)
            #pragma unroll
            for (int j = 0; j < 8; j++)
                mma_tf32(acc[i][j], a[i], b[j]);
    }

    // Epilogue: exp and stream to P.
    #pragma unroll
    for (int i = 0; i < 2; i++) {
        int row = q0 + wm * 32 + i * 16;
        #pragma unroll
        for (int j = 0; j < 8; j++) {
            int col = k0 + wn * 64 + j * 8 + 2 * r;
            float2 v0 = make_float2(__expf(acc[i][j][0]), __expf(acc[i][j][1]));
            float2 v1 = make_float2(__expf(acc[i][j][2]), __expf(acc[i][j][3]));
            *reinterpret_cast<float2*>(&ph[(size_t)(row + g)     * SEQ + col]) = v0;
            *reinterpret_cast<float2*>(&ph[(size_t)(row + g + 8) * SEQ + col]) = v1;
        }
    }
}

// --------------------------------------------------------------------------
// pv_norm: ctx[q, h*64:+64] = (P_h @ V_h) / rowsum(P_h)
// One CTA per (128-query tile, head); sweeps K=2048 in BK=32 steps.
// Row sums accumulated during P staging (each element passes once).
// As [128][36] (4g+r conflict-free), Bs [32][72] (8r+g conflict-free).
// --------------------------------------------------------------------------
#define PA 36
#define PB 72
__global__ __launch_bounds__(256) void pv_norm(
    const float* __restrict__ p, const float* __restrict__ v,
    float* __restrict__ ctx)
{
    __shared__ unsigned As[128 * PA];
    __shared__ unsigned Bs[32 * PB];
    __shared__ float rsum[128];

    const int tid  = threadIdx.x;
    const int lane = tid & 31;
    const int warp = tid >> 5;
    const int g = lane >> 2;
    const int r = lane & 3;
    const int qb = warp * 16;

    const int m0 = blockIdx.x * 128;
    const int h  = blockIdx.y;
    const float* ph = p + (size_t)h * SEQ * SEQ;

    const int mrow = tid >> 3;   // 0..31 (row group within 32-row band)
    const int q8   = tid & 7;    // float4 slot within 32-wide k chunk

    float rs[4] = {0.f, 0.f, 0.f, 0.f};
    float o[8][4];
    #pragma unroll
    for (int j = 0; j < 8; j++)
        #pragma unroll
        for (int t = 0; t < 4; t++) o[j][t] = 0.f;

    for (int k0 = 0; k0 < SEQ; k0 += 32) {
        // Stage V tile [32 keys][64 dims]
        #pragma unroll
        for (int e = 0; e < 2; e++) {
            int kk = e * 16 + (tid >> 4);
            int f4 = tid & 15;
            float4 v4 = *reinterpret_cast<const float4*>(
                &v[(size_t)(k0 + kk) * DM + h * HD + f4 * 4]);
            unsigned* bp = &Bs[kk * PB + f4 * 4];
            bp[0] = f2tf(v4.x);
            bp[1] = f2tf(v4.y);
            bp[2] = f2tf(v4.z);
            bp[3] = f2tf(v4.w);
        }
        // Stage P tile [128 rows][32 keys] + accumulate row sums
        #pragma unroll
        for (int e = 0; e < 4; e++) {
            int m = e * 32 + mrow;
            float4 p4 = *reinterpret_cast<const float4*>(
                &ph[(size_t)(m0 + m) * SEQ + k0 + q8 * 4]);
            rs[e] += (p4.x + p4.y) + (p4.z + p4.w);
            unsigned* ap = &As[m * PA + q8 * 4];
            ap[0] = f2tf(p4.x);
            ap[1] = f2tf(p4.y);
            ap[2] = f2tf(p4.z);
            ap[3] = f2tf(p4.w);
        }
        __syncthreads();

        #pragma unroll
        for (int kt = 0; kt < 4; kt++) {
            const int kk = kt * 8;
            unsigned a[4], b[8][2];
            a[0] = As[(qb + g)     * PA + kk + r];
            a[1] = As[(qb + g + 8) * PA + kk + r];
            a[2] = As[(qb + g)     * PA + kk + r + 4];
            a[3] = As[(qb + g + 8) * PA + kk + r + 4];
            #pragma unroll
            for (int nt = 0; nt < 8; nt++) {
                b[nt][0] = Bs[(kk + r)     * PB + nt * 8 + g];
                b[nt][1] = Bs[(kk + r + 4) * PB + nt * 8 + g];
            }
            #pragma unroll
            for (int nt = 0; nt < 8; nt++)
                mma_tf32(o[nt], a, b[nt]);
        }
        __syncthreads();
    }

    // Finalize row sums: reduce across the 8 lanes sharing each row.
    #pragma unroll
    for (int e = 0; e < 4; e++) {
        float s = rs[e];
        s += __shfl_xor_sync(0xffffffffu, s, 1);
        s += __shfl_xor_sync(0xffffffffu, s, 2);
        s += __shfl_xor_sync(0xffffffffu, s, 4);
        if ((tid & 7) == 0) rsum[e * 32 + mrow] = s;
    }
    __syncthreads();

    float inv0 = 1.0f / rsum[qb + g];
    float inv1 = 1.0f / rsum[qb + g + 8];
    #pragma unroll
    for (int nt = 0; nt < 8; nt++) {
        int col = h * HD + nt * 8 + 2 * r;
        float2 v0 = make_float2(o[nt][0] * inv0, o[nt][1] * inv0);
        float2 v1 = make_float2(o[nt][2] * inv1, o[nt][3] * inv1);
        *reinterpret_cast<float2*>(&ctx[(size_t)(m0 + qb + g)     * DM + col]) = v0;
        *reinterpret_cast<float2*>(&ctx[(size_t)(m0 + qb + g + 8) * DM + col]) = v1;
    }
}

// --------------------------------------------------------------------------
// Launcher
// --------------------------------------------------------------------------
extern "C" void kernel_launch(void* const* d_in, const int* in_sizes, int n_in,
                              void* d_out, int out_size)
{
    const float* X    = (const float*)d_in[0];
    const float* Wq   = (const float*)d_in[1];
    const float* Wdkv = (const float*)d_in[2];
    const float* Wuk  = (const float*)d_in[3];
    const float* Wuv  = (const float*)d_in[4];
    const float* Wo   = (const float*)d_in[5];
    const float* wW   = (const float*)d_in[6];
    const float* wb   = (const float*)d_in[7];
    float* out = (float*)d_out;

    float *q, *ckv, *kk, *vv, *ctx, *pp;
    cudaGetSymbolAddress((void**)&q,   g_q);
    cudaGetSymbolAddress((void**)&ckv, g_ckv);
    cudaGetSymbolAddress((void**)&kk,  g_k);
    cudaGetSymbolAddress((void**)&vv,  g_v);
    cudaGetSymbolAddress((void**)&ctx, g_ctx);
    cudaGetSymbolAddress((void**)&pp,  g_p);

    // Projections
    gemm_tc<<<dim3(DM / 128, SEQ / 128, 1), 256>>>(X, Wq, nullptr, q,
                                                   SEQ, DM, DM, DM, DM, DM);
    gemm_tc<<<dim3(LAT / 128, SEQ / 128, 1), 256>>>(X, Wdkv, nullptr, ckv,
                                                    SEQ, LAT, DM, DM, LAT, LAT);
    gemm_tc<<<dim3(DM / 128, SEQ / 128, 1), 256>>>(ckv, Wuk, nullptr, kk,
                                                   SEQ, DM, LAT, LAT, DM, DM);
    gemm_tc<<<dim3(DM / 128, SEQ / 128, 1), 256>>>(ckv, Wuv, nullptr, vv,
                                                   SEQ, DM, LAT, LAT, DM, DM);

    // Attention as two GEMM-shaped passes
    const int ssmem = 2 * 128 * SP * (int)sizeof(unsigned);  // 69632 B
    cudaFuncSetAttribute(score_exp, cudaFuncAttributeMaxDynamicSharedMemorySize, ssmem);
    score_exp<<<dim3(SEQ / 128, SEQ / 128, NH), 256, ssmem>>>(q, kk, pp);
    pv_norm<<<dim3(SEQ / 128, NH, 1), 256>>>(pp, vv, ctx);

    // Output projections
    gemm_tc<<<dim3(DM / 128, SEQ / 128, 1), 256>>>(ctx, Wo, nullptr, out,
                                                   SEQ, DM, DM, DM, DM, 2048);
    gemm_tc<<<dim3(256 / 128, SEQ / 128, 4), 256>>>(out, wW, wb, out + 1024,
                                                    SEQ, 256, DM, 2048, 256, 2048);
}

// round 8
// speedup vs baseline: 1.0068x; 1.0068x over previous
#include <cuda_runtime.h>
#include <math.h>

#define SEQ 2048
#define DM  1024
#define NH  16
#define HD  64
#define LAT 256

// Scratch — device globals (no allocation allowed).
__device__ float g_q[SEQ * DM];
__device__ float g_ckv[SEQ * LAT];
__device__ float g_k[SEQ * DM];
__device__ float g_v[SEQ * DM];
__device__ float g_ctx[SEQ * DM];

// --------------------------------------------------------------------------
// tf32 helpers
// --------------------------------------------------------------------------
__device__ __forceinline__ unsigned f2tf(float x) {
    unsigned r;
    asm("cvt.rna.tf32.f32 %0, %1;" : "=r"(r) : "f"(x));
    return r;
}

__device__ __forceinline__ void mma_tf32(float* c, const unsigned* a, const unsigned* b) {
    asm volatile(
        "mma.sync.aligned.m16n8k8.row.col.f32.tf32.tf32.f32 "
        "{%0,%1,%2,%3}, {%4,%5,%6,%7}, {%8,%9}, {%0,%1,%2,%3};"
        : "+f"(c[0]), "+f"(c[1]), "+f"(c[2]), "+f"(c[3])
        : "r"(a[0]), "r"(a[1]), "r"(a[2]), "r"(a[3]),
          "r"(b[0]), "r"(b[1]));
}

// --------------------------------------------------------------------------
// tf32 tensor-core GEMM. CTA tile 128x128, BK=64 (halved barrier count),
// 8 warps (4m x 2n), warp tile 32x64. Dynamic smem 68608 B.
// ocvt!=0: output written as tf32-converted bits of (val*oscale) — feeds
// flash without any further conversion (bit-identical numerics).
// --------------------------------------------------------------------------
#define GAP 68    // As row stride (64+4): 4g+r bank-distinct
#define GBP 132   // Bs row stride: 4r+g bank-distinct
__global__ __launch_bounds__(256) void gemm_tc(
    const float* __restrict__ A, const float* __restrict__ B,
    const float* __restrict__ bias, float* __restrict__ C,
    int M, int N, int K, int lda, int ldb, int ldc,
    float oscale, int ocvt)
{
    extern __shared__ unsigned gsm[];
    unsigned* As = gsm;               // 128*68
    unsigned* Bs = gsm + 128 * GAP;   // 64*132

    const int tid  = threadIdx.x;
    const int lane = tid & 31;
    const int warp = tid >> 5;
    const int g = lane >> 2;
    const int r = lane & 3;
    const int wm = warp & 3;
    const int wn = warp >> 2;

    const int m0 = blockIdx.y * 128;
    const int n0 = blockIdx.x * 128;
    const int z  = blockIdx.z;
    B += (long)z * K * N;
    C += (long)z * N;
    const float* bptr = bias ? bias + (long)z * N : nullptr;

    float acc[2][8][4];
    #pragma unroll
    for (int i = 0; i < 2; i++)
        #pragma unroll
        for (int j = 0; j < 8; j++)
            #pragma unroll
            for (int t = 0; t < 4; t++) acc[i][j][t] = 0.f;

    for (int k0 = 0; k0 < K; k0 += 64) {
        // A tile 128x64 -> As[m][k]
        #pragma unroll
        for (int e = 0; e < 32; e++) {
            int idx = e * 256 + tid;
            int m = idx >> 6, kk = idx & 63;
            As[m * GAP + kk] = f2tf(A[(long)(m0 + m) * lda + k0 + kk]);
        }
        // B tile 64x128 -> Bs[k][n]
        #pragma unroll
        for (int e = 0; e < 32; e++) {
            int idx = e * 256 + tid;
            int kk = idx >> 7, n = idx & 127;
            Bs[kk * GBP + n] = f2tf(B[(long)(k0 + kk) * ldb + n0 + n]);
        }
        __syncthreads();

        #pragma unroll
        for (int ks = 0; ks < 8; ks++) {
            const int k = ks * 8;
            unsigned a[2][4], b[8][2];
            #pragma unroll
            for (int i = 0; i < 2; i++) {
                int row = wm * 32 + i * 16;
                a[i][0] = As[(row + g)     * GAP + k + r];
                a[i][1] = As[(row + g + 8) * GAP + k + r];
                a[i][2] = As[(row + g)     * GAP + k + r + 4];
                a[i][3] = As[(row + g + 8) * GAP + k + r + 4];
            }
            #pragma unroll
            for (int j = 0; j < 8; j++) {
                int col = wn * 64 + j * 8;
                b[j][0] = Bs[(k + r)     * GBP + col + g];
                b[j][1] = Bs[(k + r + 4) * GBP + col + g];
            }
            #pragma unroll
            for (int i = 0; i < 2; i++)
                #pragma unroll
                for (int j = 0; j < 8; j++)
                    mma_tf32(acc[i][j], a[i], b[j]);
        }
        __syncthreads();
    }

    #pragma unroll
    for (int i = 0; i < 2; i++) {
        int row = m0 + wm * 32 + i * 16;
        #pragma unroll
        for (int j = 0; j < 8; j++) {
            int col = n0 + wn * 64 + j * 8 + 2 * r;
            float b0 = 0.f, b1 = 0.f;
            if (bptr) { b0 = bptr[col]; b1 = bptr[col + 1]; }
            float c00 = acc[i][j][0] + b0, c01 = acc[i][j][1] + b1;
            float c10 = acc[i][j][2] + b0, c11 = acc[i][j][3] + b1;
            if (ocvt) {
                c00 = __uint_as_float(f2tf(c00 * oscale));
                c01 = __uint_as_float(f2tf(c01 * oscale));
                c10 = __uint_as_float(f2tf(c10 * oscale));
                c11 = __uint_as_float(f2tf(c11 * oscale));
            }
            float2 v0 = make_float2(c00, c01);
            float2 v1 = make_float2(c10, c11);
            *reinterpret_cast<float2*>(&C[(long)(row + g)     * ldc + col]) = v0;
            *reinterpret_cast<float2*>(&C[(long)(row + g + 8) * ldc + col]) = v1;
        }
    }
}

// --------------------------------------------------------------------------
// Flash v6: identical to proven v5 (key-split halves, 2 CTAs/SM) except
// q/k/v arrive pre-converted to tf32 bits (q pre-scaled) -> staging is a
// pure bit copy (no cvt in the LDG->STS chain). qofs allows query-range
// splitting across launches.
// --------------------------------------------------------------------------
__global__ __launch_bounds__(256, 2) void flash_tc6(
    const float* __restrict__ q, const float* __restrict__ k,
    const float* __restrict__ v, float* __restrict__ ctx, int qofs)
{
    extern __shared__ unsigned smx[];
    unsigned* KB = smx;              // 5120
    unsigned* VB = smx + 5120;       // 6656
    unsigned* QB = smx + 11776;      // 10752

    const int tid  = threadIdx.x;
    const int lane = tid & 31;
    const int warp = tid >> 5;
    const int g = lane >> 2;
    const int r = lane & 3;
    const int h  = blockIdx.y;
    const int i0 = qofs + blockIdx.x * 128;
    const int wbase = warp * 1344;

    // ---- Stage Q (already tf32 bits, pre-scaled) into QB ----
    #pragma unroll
    for (int e = 0; e < 8; e++) {
        int idx = e * 256 + tid;
        int row = idx >> 4, dq = idx & 15;
        uint4 q4 = *reinterpret_cast<const uint4*>(
            &q[(long)(i0 + row) * DM + h * HD + dq * 4]);
        unsigned* p = &QB[(row >> 4) * 1344 + (row & 15) * 84 + dq];
        p[0]  = q4.x;
        p[20] = q4.y;
        p[40] = q4.z;
        p[60] = q4.w;
    }
    __syncthreads();

    // ---- Extract Q A-fragments ----
    unsigned qa[8][4];
    {
        const uint4* lo4 = reinterpret_cast<const uint4*>(&QB[wbase + g * 84 + r * 20]);
        const uint4* hi4 = reinterpret_cast<const uint4*>(&QB[wbase + (g + 8) * 84 + r * 20]);
        uint4 L[4] = {lo4[0], lo4[1], lo4[2], lo4[3]};
        uint4 H[4] = {hi4[0], hi4[1], hi4[2], hi4[3]};
        const unsigned* lo = reinterpret_cast<const unsigned*>(L);
        const unsigned* hi = reinterpret_cast<const unsigned*>(H);
        #pragma unroll
        for (int kt = 0; kt < 8; kt++) {
            qa[kt][0] = lo[2 * kt];
            qa[kt][1] = hi[2 * kt];
            qa[kt][2] = lo[2 * kt + 1];
            qa[kt][3] = hi[2 * kt + 1];
        }
    }

    float l0 = 0.f, l1 = 0.f;
    float o[8][4];
    #pragma unroll
    for (int j = 0; j < 8; j++)
        #pragma unroll
        for (int t = 0; t < 4; t++) o[j][t] = 0.f;

    for (int j0 = 0; j0 < SEQ; j0 += 64) {
        // ---- Stage K, V tiles (pure bit copy) ----
        #pragma unroll
        for (int e = 0; e < 4; e++) {
            int idx = e * 256 + tid;
            int key = idx >> 4, dq = idx & 15;
            long gbase = (long)(j0 + key) * DM + h * HD + dq * 4;
            uint4 k4 = *reinterpret_cast<const uint4*>(&k[gbase]);
            uint4 v4 = *reinterpret_cast<const uint4*>(&v[gbase]);
            unsigned* kp = &KB[key * 80 + dq];
            kp[0]  = k4.x;
            kp[20] = k4.y;
            kp[40] = k4.z;
            kp[60] = k4.w;
            int c8b = (dq & 1) * 4;
            unsigned* vp = &VB[key * 104 + c8b * 12 + (dq >> 1)];
            vp[0]  = v4.x;
            vp[12] = v4.y;
            vp[24] = v4.z;
            vp[36] = v4.w;
        }
        __syncthreads();

        // ---- Two 32-key halves; s/pa registers reused ----
        #pragma unroll
        for (int half = 0; half < 2; half++) {
            const int nb = half * 4;

            float s[4][4];
            #pragma unroll
            for (int nt = 0; nt < 4; nt++) {
                #pragma unroll
                for (int t = 0; t < 4; t++) s[nt][t] = 0.f;
                const uint4* kp4 = reinterpret_cast<const uint4*>(
                    &KB[((nb + nt) * 8 + g) * 80 + r * 20]);
                uint4 W[4] = {kp4[0], kp4[1], kp4[2], kp4[3]};
                const unsigned* w = reinterpret_cast<const unsigned*>(W);
                #pragma unroll
                for (int kt = 0; kt < 8; kt++) {
                    unsigned b[2] = {w[2 * kt], w[2 * kt + 1]};
                    mma_tf32(s[nt], qa[kt], b);
                }
            }

            #pragma unroll
            for (int nt = 0; nt < 4; nt++) {
                s[nt][0] = __expf(s[nt][0]);
                s[nt][1] = __expf(s[nt][1]);
                s[nt][2] = __expf(s[nt][2]);
                s[nt][3] = __expf(s[nt][3]);
                l0 += s[nt][0] + s[nt][1];
                l1 += s[nt][2] + s[nt][3];
            }

            {
                int cc = (2 * r) & 3;
                int jb = r >> 1;
                unsigned* plo = &QB[wbase + g * 84 + cc * 20 + jb];
                unsigned* phi = &QB[wbase + (g + 8) * 84 + cc * 20 + jb];
                #pragma unroll
                for (int nt = 0; nt < 4; nt++) {
                    int wofs = 2 * (nb + nt);
                    plo[wofs]      = f2tf(s[nt][0]);
                    plo[wofs + 20] = f2tf(s[nt][1]);
                    phi[wofs]      = f2tf(s[nt][2]);
                    phi[wofs + 20] = f2tf(s[nt][3]);
                }
            }
            __syncwarp();

            unsigned pa[4][4];
            {
                const uint4* lo4 = reinterpret_cast<const uint4*>(
                    &QB[wbase + g * 84 + r * 20 + 2 * nb]);
                const uint4* hi4 = reinterpret_cast<const uint4*>(
                    &QB[wbase + (g + 8) * 84 + r * 20 + 2 * nb]);
                uint4 L[2] = {lo4[0], lo4[1]};
                uint4 H[2] = {hi4[0], hi4[1]};
                const unsigned* lo = reinterpret_cast<const unsigned*>(L);
                const unsigned* hi = reinterpret_cast<const unsigned*>(H);
                #pragma unroll
                for (int kt = 0; kt < 4; kt++) {
                    pa[kt][0] = lo[2 * kt];
                    pa[kt][1] = hi[2 * kt];
                    pa[kt][2] = lo[2 * kt + 1];
                    pa[kt][3] = hi[2 * kt + 1];
                }
            }

            #pragma unroll
            for (int kt = 0; kt < 4; kt++) {
                const uint4* va4 = reinterpret_cast<const uint4*>(
                    &VB[(8 * (nb + kt) + r) * 104 + g * 12]);
                const uint4* vb4 = reinterpret_cast<const uint4*>(
                    &VB[(8 * (nb + kt) + r + 4) * 104 + g * 12]);
                uint4 A0 = va4[0], A1 = va4[1], B0 = vb4[0], B1 = vb4[1];
                unsigned waa[8] = {A0.x, A0.y, A0.z, A0.w, A1.x, A1.y, A1.z, A1.w};
                unsigned wbb[8] = {B0.x, B0.y, B0.z, B0.w, B1.x, B1.y, B1.z, B1.w};
                #pragma unroll
                for (int nt = 0; nt < 8; nt++) {
                    unsigned b[2] = {waa[nt], wbb[nt]};
                    mma_tf32(o[nt], pa[kt], b);
                }
            }
            __syncwarp();
        }
        __syncthreads();
    }

    // ---- Row sums, normalize, write ctx ----
    l0 += __shfl_xor_sync(0xffffffffu, l0, 1);
    l0 += __shfl_xor_sync(0xffffffffu, l0, 2);
    l1 += __shfl_xor_sync(0xffffffffu, l1, 1);
    l1 += __shfl_xor_sync(0xffffffffu, l1, 2);
    float inv0 = 1.0f / l0, inv1 = 1.0f / l1;
    const int qb = warp * 16;
    #pragma unroll
    for (int nt = 0; nt < 8; nt++) {
        int col = h * HD + nt * 8 + 2 * r;
        float2 v0 = make_float2(o[nt][0] * inv0, o[nt][1] * inv0);
        float2 v1 = make_float2(o[nt][2] * inv1, o[nt][3] * inv1);
        *reinterpret_cast<float2*>(&ctx[(long)(i0 + qb + g)     * DM + col]) = v0;
        *reinterpret_cast<float2*>(&ctx[(long)(i0 + qb + g + 8) * DM + col]) = v1;
    }
}

// --------------------------------------------------------------------------
// Launcher
// --------------------------------------------------------------------------
extern "C" void kernel_launch(void* const* d_in, const int* in_sizes, int n_in,
                              void* d_out, int out_size)
{
    const float* X    = (const float*)d_in[0];
    const float* Wq   = (const float*)d_in[1];
    const float* Wdkv = (const float*)d_in[2];
    const float* Wuk  = (const float*)d_in[3];
    const float* Wuv  = (const float*)d_in[4];
    const float* Wo   = (const float*)d_in[5];
    const float* wW   = (const float*)d_in[6];
    const float* wb   = (const float*)d_in[7];
    float* out = (float*)d_out;

    float *q, *ckv, *kk, *vv, *ctx;
    cudaGetSymbolAddress((void**)&q,   g_q);
    cudaGetSymbolAddress((void**)&ckv, g_ckv);
    cudaGetSymbolAddress((void**)&kk,  g_k);
    cudaGetSymbolAddress((void**)&vv,  g_v);
    cudaGetSymbolAddress((void**)&ctx, g_ctx);

    const int gsmem = (128 * GAP + 64 * GBP) * (int)sizeof(unsigned);  // 68608
    cudaFuncSetAttribute(gemm_tc, cudaFuncAttributeMaxDynamicSharedMemorySize, gsmem);
    const int fsmem = 22528 * (int)sizeof(unsigned);  // 90112
    cudaFuncSetAttribute(flash_tc6, cudaFuncAttributeMaxDynamicSharedMemorySize, fsmem);

    // q = tf32(0.125 * X @ Wq)   (pre-scaled, pre-converted)
    gemm_tc<<<dim3(DM / 128, SEQ / 128, 1), 256, gsmem>>>(
        X, Wq, nullptr, q, SEQ, DM, DM, DM, DM, DM, 0.125f, 1);
    // c_kv (plain fp32 — consumed by k/v gemms)
    gemm_tc<<<dim3(LAT / 128, SEQ / 128, 1), 256, gsmem>>>(
        X, Wdkv, nullptr, ckv, SEQ, LAT, DM, DM, LAT, LAT, 1.0f, 0);
    // k, v = tf32(c_kv @ Wuk/Wuv)
    gemm_tc<<<dim3(DM / 128, SEQ / 128, 1), 256, gsmem>>>(
        ckv, Wuk, nullptr, kk, SEQ, DM, LAT, LAT, DM, DM, 1.0f, 1);
    gemm_tc<<<dim3(DM / 128, SEQ / 128, 1), 256, gsmem>>>(
        ckv, Wuv, nullptr, vv, SEQ, DM, LAT, LAT, DM, DM, 1.0f, 1);

    // attention, split into two query ranges (profiling coverage + same work)
    flash_tc6<<<dim3(8, NH, 1), 256, fsmem>>>(q, kk, vv, ctx, 0);
    flash_tc6<<<dim3(8, NH, 1), 256, fsmem>>>(q, kk, vv, ctx, 1024);

    // body, wheels (plain fp32)
    gemm_tc<<<dim3(DM / 128, SEQ / 128, 1), 256, gsmem>>>(
        ctx, Wo, nullptr, out, SEQ, DM, DM, DM, DM, 2048, 1.0f, 0);
    gemm_tc<<<dim3(256 / 128, SEQ / 128, 4), 256, gsmem>>>(
        out, wW, wb, out + 1024, SEQ, 256, DM, 2048, 256, 2048, 1.0f, 0);
}

// round 9
// speedup vs baseline: 1.3085x; 1.2997x over previous
#include <cuda_runtime.h>
#include <math.h>

#define SEQ 2048
#define DM  1024
#define NH  16
#define HD  64
#define LAT 256

// Scratch — device globals (no allocation allowed).
__device__ float g_q[SEQ * DM];
__device__ float g_ckv[SEQ * LAT];
__device__ float g_k[SEQ * DM];
__device__ float g_v[SEQ * DM];
__device__ float g_ctx[SEQ * DM];

// --------------------------------------------------------------------------
// tf32 helpers
// --------------------------------------------------------------------------
__device__ __forceinline__ unsigned f2tf(float x) {
    unsigned r;
    asm("cvt.rna.tf32.f32 %0, %1;" : "=r"(r) : "f"(x));
    return r;
}

__device__ __forceinline__ void mma_tf32(float* c, const unsigned* a, const unsigned* b) {
    asm volatile(
        "mma.sync.aligned.m16n8k8.row.col.f32.tf32.tf32.f32 "
        "{%0,%1,%2,%3}, {%4,%5,%6,%7}, {%8,%9}, {%0,%1,%2,%3};"
        : "+f"(c[0]), "+f"(c[1]), "+f"(c[2]), "+f"(c[3])
        : "r"(a[0]), "r"(a[1]), "r"(a[2]), "r"(a[3]),
          "r"(b[0]), "r"(b[1]));
}

// --------------------------------------------------------------------------
// tf32 tensor-core GEMM — proven R6 config (BK=32, static smem, no reg cap,
// 23.5us). OCVT is compile-time: true-instantiation converts the output to
// tf32 bits (times OSCALE_NUM/OSCALE_DEN) in the epilogue only.
// --------------------------------------------------------------------------
#define AP 36
#define BP 132
template <bool OCVT, int OSHIFT>   // OCVT: tf32-convert out; scale = 2^-OSHIFT
__global__ __launch_bounds__(256) void gemm_tc(
    const float* __restrict__ A, const float* __restrict__ B,
    const float* __restrict__ bias, float* __restrict__ C,
    int M, int N, int K, int lda, int ldb, int ldc)
{
    __shared__ unsigned As[128 * AP];
    __shared__ unsigned Bs[32 * BP];

    const int tid  = threadIdx.x;
    const int lane = tid & 31;
    const int warp = tid >> 5;
    const int g = lane >> 2;
    const int r = lane & 3;
    const int wm = warp & 3;
    const int wn = warp >> 2;

    const int m0 = blockIdx.y * 128;
    const int n0 = blockIdx.x * 128;
    const int z  = blockIdx.z;
    B += (long)z * K * N;
    C += (long)z * N;
    const float* bptr = bias ? bias + (long)z * N : nullptr;

    float acc[2][8][4];
    #pragma unroll
    for (int i = 0; i < 2; i++)
        #pragma unroll
        for (int j = 0; j < 8; j++)
            #pragma unroll
            for (int t = 0; t < 4; t++) acc[i][j][t] = 0.f;

    for (int k0 = 0; k0 < K; k0 += 32) {
        #pragma unroll
        for (int e = 0; e < 16; e++) {
            int idx = e * 256 + tid;
            int m = idx >> 5, kk = idx & 31;
            As[m * AP + kk] = f2tf(A[(long)(m0 + m) * lda + k0 + kk]);
        }
        #pragma unroll
        for (int e = 0; e < 16; e++) {
            int idx = e * 256 + tid;
            int kk = idx >> 7, n = idx & 127;
            Bs[kk * BP + n] = f2tf(B[(long)(k0 + kk) * ldb + n0 + n]);
        }
        __syncthreads();

        #pragma unroll
        for (int ks = 0; ks < 4; ks++) {
            const int k = ks * 8;
            unsigned a[2][4], b[8][2];
            #pragma unroll
            for (int i = 0; i < 2; i++) {
                int row = wm * 32 + i * 16;
                a[i][0] = As[(row + g)     * AP + k + r];
                a[i][1] = As[(row + g + 8) * AP + k + r];
                a[i][2] = As[(row + g)     * AP + k + r + 4];
                a[i][3] = As[(row + g + 8) * AP + k + r + 4];
            }
            #pragma unroll
            for (int j = 0; j < 8; j++) {
                int col = wn * 64 + j * 8;
                b[j][0] = Bs[(k + r)     * BP + col + g];
                b[j][1] = Bs[(k + r + 4) * BP + col + g];
            }
            #pragma unroll
            for (int i = 0; i < 2; i++)
                #pragma unroll
                for (int j = 0; j < 8; j++)
                    mma_tf32(acc[i][j], a[i], b[j]);
        }
        __syncthreads();
    }

    const float osc = 1.0f / (float)(1 << OSHIFT);
    #pragma unroll
    for (int i = 0; i < 2; i++) {
        int row = m0 + wm * 32 + i * 16;
        #pragma unroll
        for (int j = 0; j < 8; j++) {
            int col = n0 + wn * 64 + j * 8 + 2 * r;
            float b0 = 0.f, b1 = 0.f;
            if (bptr) { b0 = bptr[col]; b1 = bptr[col + 1]; }
            float c00 = acc[i][j][0] + b0, c01 = acc[i][j][1] + b1;
            float c10 = acc[i][j][2] + b0, c11 = acc[i][j][3] + b1;
            if (OCVT) {
                c00 = __uint_as_float(f2tf(c00 * osc));
                c01 = __uint_as_float(f2tf(c01 * osc));
                c10 = __uint_as_float(f2tf(c10 * osc));
                c11 = __uint_as_float(f2tf(c11 * osc));
            }
            *reinterpret_cast<float2*>(&C[(long)(row + g) * ldc + col]) =
                make_float2(c00, c01);
            *reinterpret_cast<float2*>(&C[(long)(row + g + 8) * ldc + col]) =
                make_float2(c10, c11);
        }
    }
}

// --------------------------------------------------------------------------
// Flash v6: exactly R6's proven flash_tc5 (key-split halves, 2 CTAs/SM,
// 8 warps / 128 queries, single 256-CTA launch) with ONE delta: q/k/v
// arrive as pre-converted tf32 bits (q pre-scaled), so staging is a pure
// uint4 bit copy — no cvt in the LDG->STS chain.
// --------------------------------------------------------------------------
__global__ __launch_bounds__(256, 2) void flash_tc6(
    const float* __restrict__ q, const float* __restrict__ k,
    const float* __restrict__ v, float* __restrict__ ctx)
{
    extern __shared__ unsigned smx[];
    unsigned* KB = smx;              // 5120
    unsigned* VB = smx + 5120;       // 6656
    unsigned* QB = smx + 11776;      // 10752

    const int tid  = threadIdx.x;
    const int lane = tid & 31;
    const int warp = tid >> 5;
    const int g = lane >> 2;
    const int r = lane & 3;
    const int h  = blockIdx.y;
    const int i0 = blockIdx.x * 128;
    const int wbase = warp * 1344;

    // ---- Stage Q (tf32 bits, pre-scaled) into QB ----
    #pragma unroll
    for (int e = 0; e < 8; e++) {
        int idx = e * 256 + tid;
        int row = idx >> 4, dq = idx & 15;
        uint4 q4 = *reinterpret_cast<const uint4*>(
            &q[(long)(i0 + row) * DM + h * HD + dq * 4]);
        unsigned* p = &QB[(row >> 4) * 1344 + (row & 15) * 84 + dq];
        p[0]  = q4.x;
        p[20] = q4.y;
        p[40] = q4.z;
        p[60] = q4.w;
    }
    __syncthreads();

    // ---- Extract Q A-fragments ----
    unsigned qa[8][4];
    {
        const uint4* lo4 = reinterpret_cast<const uint4*>(&QB[wbase + g * 84 + r * 20]);
        const uint4* hi4 = reinterpret_cast<const uint4*>(&QB[wbase + (g + 8) * 84 + r * 20]);
        uint4 L[4] = {lo4[0], lo4[1], lo4[2], lo4[3]};
        uint4 H[4] = {hi4[0], hi4[1], hi4[2], hi4[3]};
        const unsigned* lo = reinterpret_cast<const unsigned*>(L);
        const unsigned* hi = reinterpret_cast<const unsigned*>(H);
        #pragma unroll
        for (int kt = 0; kt < 8; kt++) {
            qa[kt][0] = lo[2 * kt];
            qa[kt][1] = hi[2 * kt];
            qa[kt][2] = lo[2 * kt + 1];
            qa[kt][3] = hi[2 * kt + 1];
        }
    }

    float l0 = 0.f, l1 = 0.f;
    float o[8][4];
    #pragma unroll
    for (int j = 0; j < 8; j++)
        #pragma unroll
        for (int t = 0; t < 4; t++) o[j][t] = 0.f;

    for (int j0 = 0; j0 < SEQ; j0 += 64) {
        // ---- Stage K, V tiles (pure bit copy) ----
        #pragma unroll
        for (int e = 0; e < 4; e++) {
            int idx = e * 256 + tid;
            int key = idx >> 4, dq = idx & 15;
            long gbase = (long)(j0 + key) * DM + h * HD + dq * 4;
            uint4 k4 = *reinterpret_cast<const uint4*>(&k[gbase]);
            uint4 v4 = *reinterpret_cast<const uint4*>(&v[gbase]);
            unsigned* kp = &KB[key * 80 + dq];
            kp[0]  = k4.x;
            kp[20] = k4.y;
            kp[40] = k4.z;
            kp[60] = k4.w;
            int c8b = (dq & 1) * 4;
            unsigned* vp = &VB[key * 104 + c8b * 12 + (dq >> 1)];
            vp[0]  = v4.x;
            vp[12] = v4.y;
            vp[24] = v4.z;
            vp[36] = v4.w;
        }
        __syncthreads();

        // ---- Two 32-key halves; s/pa registers reused ----
        #pragma unroll
        for (int half = 0; half < 2; half++) {
            const int nb = half * 4;

            float s[4][4];
            #pragma unroll
            for (int nt = 0; nt < 4; nt++) {
                #pragma unroll
                for (int t = 0; t < 4; t++) s[nt][t] = 0.f;
                const uint4* kp4 = reinterpret_cast<const uint4*>(
                    &KB[((nb + nt) * 8 + g) * 80 + r * 20]);
                uint4 W[4] = {kp4[0], kp4[1], kp4[2], kp4[3]};
                const unsigned* w = reinterpret_cast<const unsigned*>(W);
                #pragma unroll
                for (int kt = 0; kt < 8; kt++) {
                    unsigned b[2] = {w[2 * kt], w[2 * kt + 1]};
                    mma_tf32(s[nt], qa[kt], b);
                }
            }

            #pragma unroll
            for (int nt = 0; nt < 4; nt++) {
                s[nt][0] = __expf(s[nt][0]);
                s[nt][1] = __expf(s[nt][1]);
                s[nt][2] = __expf(s[nt][2]);
                s[nt][3] = __expf(s[nt][3]);
                l0 += s[nt][0] + s[nt][1];
                l1 += s[nt][2] + s[nt][3];
            }

            {
                int cc = (2 * r) & 3;
                int jb = r >> 1;
                unsigned* plo = &QB[wbase + g * 84 + cc * 20 + jb];
                unsigned* phi = &QB[wbase + (g + 8) * 84 + cc * 20 + jb];
                #pragma unroll
                for (int nt = 0; nt < 4; nt++) {
                    int wofs = 2 * (nb + nt);
                    plo[wofs]      = f2tf(s[nt][0]);
                    plo[wofs + 20] = f2tf(s[nt][1]);
                    phi[wofs]      = f2tf(s[nt][2]);
                    phi[wofs + 20] = f2tf(s[nt][3]);
                }
            }
            __syncwarp();

            unsigned pa[4][4];
            {
                const uint4* lo4 = reinterpret_cast<const uint4*>(
                    &QB[wbase + g * 84 + r * 20 + 2 * nb]);
                const uint4* hi4 = reinterpret_cast<const uint4*>(
                    &QB[wbase + (g + 8) * 84 + r * 20 + 2 * nb]);
                uint4 L[2] = {lo4[0], lo4[1]};
                uint4 H[2] = {hi4[0], hi4[1]};
                const unsigned* lo = reinterpret_cast<const unsigned*>(L);
                const unsigned* hi = reinterpret_cast<const unsigned*>(H);
                #pragma unroll
                for (int kt = 0; kt < 4; kt++) {
                    pa[kt][0] = lo[2 * kt];
                    pa[kt][1] = hi[2 * kt];
                    pa[kt][2] = lo[2 * kt + 1];
                    pa[kt][3] = hi[2 * kt + 1];
                }
            }

            #pragma unroll
            for (int kt = 0; kt < 4; kt++) {
                const uint4* va4 = reinterpret_cast<const uint4*>(
                    &VB[(8 * (nb + kt) + r) * 104 + g * 12]);
                const uint4* vb4 = reinterpret_cast<const uint4*>(
                    &VB[(8 * (nb + kt) + r + 4) * 104 + g * 12]);
                uint4 A0 = va4[0], A1 = va4[1], B0 = vb4[0], B1 = vb4[1];
                unsigned waa[8] = {A0.x, A0.y, A0.z, A0.w, A1.x, A1.y, A1.z, A1.w};
                unsigned wbb[8] = {B0.x, B0.y, B0.z, B0.w, B1.x, B1.y, B1.z, B1.w};
                #pragma unroll
                for (int nt = 0; nt < 8; nt++) {
                    unsigned b[2] = {waa[nt], wbb[nt]};
                    mma_tf32(o[nt], pa[kt], b);
                }
            }
            __syncwarp();
        }
        __syncthreads();
    }

    // ---- Row sums, normalize, write ctx ----
    l0 += __shfl_xor_sync(0xffffffffu, l0, 1);
    l0 += __shfl_xor_sync(0xffffffffu, l0, 2);
    l1 += __shfl_xor_sync(0xffffffffu, l1, 1);
    l1 += __shfl_xor_sync(0xffffffffu, l1, 2);
    float inv0 = 1.0f / l0, inv1 = 1.0f / l1;
    const int qb = warp * 16;
    #pragma unroll
    for (int nt = 0; nt < 8; nt++) {
        int col = h * HD + nt * 8 + 2 * r;
        float2 v0 = make_float2(o[nt][0] * inv0, o[nt][1] * inv0);
        float2 v1 = make_float2(o[nt][2] * inv1, o[nt][3] * inv1);
        *reinterpret_cast<float2*>(&ctx[(long)(i0 + qb + g)     * DM + col]) = v0;
        *reinterpret_cast<float2*>(&ctx[(long)(i0 + qb + g + 8) * DM + col]) = v1;
    }
}

// --------------------------------------------------------------------------
// Launcher
// --------------------------------------------------------------------------
extern "C" void kernel_launch(void* const* d_in, const int* in_sizes, int n_in,
                              void* d_out, int out_size)
{
    const float* X    = (const float*)d_in[0];
    const float* Wq   = (const float*)d_in[1];
    const float* Wdkv = (const float*)d_in[2];
    const float* Wuk  = (const float*)d_in[3];
    const float* Wuv  = (const float*)d_in[4];
    const float* Wo   = (const float*)d_in[5];
    const float* wW   = (const float*)d_in[6];
    const float* wb   = (const float*)d_in[7];
    float* out = (float*)d_out;

    float *q, *ckv, *kk, *vv, *ctx;
    cudaGetSymbolAddress((void**)&q,   g_q);
    cudaGetSymbolAddress((void**)&ckv, g_ckv);
    cudaGetSymbolAddress((void**)&kk,  g_k);
    cudaGetSymbolAddress((void**)&vv,  g_v);
    cudaGetSymbolAddress((void**)&ctx, g_ctx);

    // q = tf32(2^-3 * (X @ Wq))  — scale folded, pre-converted
    gemm_tc<true, 3><<<dim3(DM / 128, SEQ / 128, 1), 256>>>(
        X, Wq, nullptr, q, SEQ, DM, DM, DM, DM, DM);
    // c_kv (plain fp32)
    gemm_tc<false, 0><<<dim3(LAT / 128, SEQ / 128, 1), 256>>>(
        X, Wdkv, nullptr, ckv, SEQ, LAT, DM, DM, LAT, LAT);
    // k, v = tf32(c_kv @ Wuk/Wuv)
    gemm_tc<true, 0><<<dim3(DM / 128, SEQ / 128, 1), 256>>>(
        ckv, Wuk, nullptr, kk, SEQ, DM, LAT, LAT, DM, DM);
    gemm_tc<true, 0><<<dim3(DM / 128, SEQ / 128, 1), 256>>>(
        ckv, Wuv, nullptr, vv, SEQ, DM, LAT, LAT, DM, DM);

    // attention (single 256-CTA launch)
    const int fsmem = 22528 * (int)sizeof(unsigned);  // 90112
    cudaFuncSetAttribute(flash_tc6, cudaFuncAttributeMaxDynamicSharedMemorySize, fsmem);
    flash_tc6<<<dim3(SEQ / 128, NH, 1), 256, fsmem>>>(q, kk, vv, ctx);

    // body, wheels (plain fp32)
    gemm_tc<false, 0><<<dim3(DM / 128, SEQ / 128, 1), 256>>>(
        ctx, Wo, nullptr, out, SEQ, DM, DM, DM, DM, 2048);
    gemm_tc<false, 0><<<dim3(256 / 128, SEQ / 128, 4), 256>>>(
        out, wW, wb, out + 1024, SEQ, 256, DM, 2048, 256, 2048);
}